// round 1
// baseline (speedup 1.0000x reference)
#include <cuda_runtime.h>
#include <math.h>

#define B_ 2
#define L_ 2048
#define E_ 1024
#define H_ 8
#define D_ 128

// Scratch (allocation-free rule: __device__ globals)
__device__ float g_Q[B_ * L_ * E_];
__device__ float g_K[B_ * L_ * E_];
__device__ float g_V[B_ * L_ * E_];
__device__ float g_ctx[B_ * L_ * E_];

// Anchor columns (Skv=2048): unique(int(r*2047)); 0 is covered by the stride-16 loop,
// the rest are all non-multiples of 16 (verified), so no duplicate visits.
__constant__ int c_anchors[10] = {204, 409, 614, 781, 1023, 1265, 1432, 1637, 1842, 2047};

// ---------------------------------------------------------------------------
// GEMM: C[m][n] = sum_k A[m*1024+k] * W[n*1024+k] + bias[n]
// A: [M,1024] row-major.  W: [1024,1024] row-major (out,in) -> NT GEMM.
// 128x128 tile, BK=16, 256 threads, 8x8 microtile (4+4 split, conflict-free).
// ---------------------------------------------------------------------------
__global__ __launch_bounds__(256, 2)
void gemm_bias_kernel(const float* __restrict__ A, const float* __restrict__ W,
                      const float* __restrict__ bias, float* __restrict__ C) {
    const int K = 1024;
    __shared__ float As[16][128];
    __shared__ float Ws[16][128];

    int tid = threadIdx.x;
    int tx = tid & 15;       // col direction
    int ty = tid >> 4;       // row direction

    const float* Ag = A + (size_t)blockIdx.y * 128 * K;
    const float* Wg = W + (size_t)blockIdx.x * 128 * K;

    // tile loaders: 128 rows x 16 cols = 512 float4; thread handles idx=tid and tid+256
    int r0 = tid >> 2;
    int r1 = (tid + 256) >> 2;
    int c0 = (tid & 3) * 4;   // same for both idx (low 2 bits unchanged by +256)

    float4 ra0 = *(const float4*)(Ag + (size_t)r0 * K + c0);
    float4 ra1 = *(const float4*)(Ag + (size_t)r1 * K + c0);
    float4 rw0 = *(const float4*)(Wg + (size_t)r0 * K + c0);
    float4 rw1 = *(const float4*)(Wg + (size_t)r1 * K + c0);

    float acc[8][8];
#pragma unroll
    for (int i = 0; i < 8; ++i)
#pragma unroll
        for (int j = 0; j < 8; ++j) acc[i][j] = 0.0f;

    for (int k0 = 0; k0 < K; k0 += 16) {
        // store staged tile to smem (transposed: [k][row])
        As[c0 + 0][r0] = ra0.x; As[c0 + 1][r0] = ra0.y; As[c0 + 2][r0] = ra0.z; As[c0 + 3][r0] = ra0.w;
        As[c0 + 0][r1] = ra1.x; As[c0 + 1][r1] = ra1.y; As[c0 + 2][r1] = ra1.z; As[c0 + 3][r1] = ra1.w;
        Ws[c0 + 0][r0] = rw0.x; Ws[c0 + 1][r0] = rw0.y; Ws[c0 + 2][r0] = rw0.z; Ws[c0 + 3][r0] = rw0.w;
        Ws[c0 + 0][r1] = rw1.x; Ws[c0 + 1][r1] = rw1.y; Ws[c0 + 2][r1] = rw1.z; Ws[c0 + 3][r1] = rw1.w;
        __syncthreads();

        // prefetch next tile (overlaps with compute)
        if (k0 + 16 < K) {
            int kn = k0 + 16;
            ra0 = *(const float4*)(Ag + (size_t)r0 * K + kn + c0);
            ra1 = *(const float4*)(Ag + (size_t)r1 * K + kn + c0);
            rw0 = *(const float4*)(Wg + (size_t)r0 * K + kn + c0);
            rw1 = *(const float4*)(Wg + (size_t)r1 * K + kn + c0);
        }

#pragma unroll
        for (int kk = 0; kk < 16; ++kk) {
            float a[8], b[8];
            *(float4*)(a)     = *(const float4*)(&As[kk][ty * 4]);
            *(float4*)(a + 4) = *(const float4*)(&As[kk][64 + ty * 4]);
            *(float4*)(b)     = *(const float4*)(&Ws[kk][tx * 4]);
            *(float4*)(b + 4) = *(const float4*)(&Ws[kk][64 + tx * 4]);
#pragma unroll
            for (int i = 0; i < 8; ++i)
#pragma unroll
                for (int j = 0; j < 8; ++j)
                    acc[i][j] += a[i] * b[j];
        }
        __syncthreads();
    }

    // writeout (N == 1024 always here)
    int row_base = blockIdx.y * 128;
    int col_base = blockIdx.x * 128;
#pragma unroll
    for (int ih = 0; ih < 2; ++ih) {
#pragma unroll
        for (int r = 0; r < 4; ++r) {
            int row = row_base + ih * 64 + ty * 4 + r;
            float* Cp = C + (size_t)row * 1024 + col_base;
#pragma unroll
            for (int jh = 0; jh < 2; ++jh) {
                int col = jh * 64 + tx * 4;
                float4 bv = *(const float4*)(bias + col_base + col);
                float4 o;
                o.x = acc[ih * 4 + r][jh * 4 + 0] + bv.x;
                o.y = acc[ih * 4 + r][jh * 4 + 1] + bv.y;
                o.z = acc[ih * 4 + r][jh * 4 + 2] + bv.z;
                o.w = acc[ih * 4 + r][jh * 4 + 3] + bv.w;
                *(float4*)(Cp + col) = o;
            }
        }
    }
}

// ---------------------------------------------------------------------------
// Sparse attention: one warp per (b, h, i). Online softmax over the exact
// allowed key set of that head's cluster.
// ---------------------------------------------------------------------------
__device__ __forceinline__ void attn_visit(
    int j, int lane,
    const float* __restrict__ Kb, const float* __restrict__ Vb,
    float q0, float q1, float q2, float q3,
    float& m, float& s, float& a0, float& a1, float& a2, float& a3)
{
    const float* kp = Kb + (size_t)j * E_;
    float d = q0 * kp[lane] + q1 * kp[lane + 32] + q2 * kp[lane + 64] + q3 * kp[lane + 96];
#pragma unroll
    for (int o = 16; o > 0; o >>= 1) d += __shfl_xor_sync(0xffffffffu, d, o);
    float score = d * 0.08838834764831845f;   // 1/sqrt(128)
    float nm = fmaxf(m, score);
    float corr = __expf(m - nm);
    float p = __expf(score - nm);
    m = nm;
    const float* vp = Vb + (size_t)j * E_;
    s  = s  * corr + p;
    a0 = a0 * corr + p * vp[lane];
    a1 = a1 * corr + p * vp[lane + 32];
    a2 = a2 * corr + p * vp[lane + 64];
    a3 = a3 * corr + p * vp[lane + 96];
}

__global__ __launch_bounds__(256)
void sparse_attn_kernel() {
    int gw   = (blockIdx.x * blockDim.x + threadIdx.x) >> 5;  // warp id == (b*H+h)*L + i
    int lane = threadIdx.x & 31;
    int i  = gw & (L_ - 1);
    int bh = gw >> 11;            // L_ = 2048
    int h  = bh & (H_ - 1);
    int b  = bh >> 3;

    const float* Qp = g_Q + ((size_t)(b * L_ + i)) * E_ + h * D_;
    float q0 = Qp[lane], q1 = Qp[lane + 32], q2 = Qp[lane + 64], q3 = Qp[lane + 96];
    const float* Kb = g_K + (size_t)b * L_ * E_ + h * D_;
    const float* Vb = g_V + (size_t)b * L_ * E_ + h * D_;

    float m = -1e30f, s = 0.0f, a0 = 0.0f, a1 = 0.0f, a2 = 0.0f, a3 = 0.0f;

    // head -> cluster: [0,3,3,1,1,1,2,2]
    int cl = (h == 0) ? 0 : (h <= 2) ? 3 : (h <= 5) ? 1 : 2;

    if (cl == 0) {                        // |i-j| <= 8, causal
        int lo = i - 8; if (lo < 0) lo = 0;
        for (int j = lo; j <= i; ++j)
            attn_visit(j, lane, Kb, Vb, q0, q1, q2, q3, m, s, a0, a1, a2, a3);
    } else if (cl == 3) {                 // |i-j| <= 16, causal
        int lo = i - 16; if (lo < 0) lo = 0;
        for (int j = lo; j <= i; ++j)
            attn_visit(j, lane, Kb, Vb, q0, q1, q2, q3, m, s, a0, a1, a2, a3);
    } else if (cl == 1) {                 // |i-j| <= 32  OR  j%8==0, causal
        int lo = i - 32; if (lo < 0) lo = 0;
        for (int j = 0; j < lo; j += 8)
            attn_visit(j, lane, Kb, Vb, q0, q1, q2, q3, m, s, a0, a1, a2, a3);
        for (int j = lo; j <= i; ++j)
            attn_visit(j, lane, Kb, Vb, q0, q1, q2, q3, m, s, a0, a1, a2, a3);
    } else {                              // j%16==0 OR anchor, causal
        for (int j = 0; j <= i; j += 16)
            attn_visit(j, lane, Kb, Vb, q0, q1, q2, q3, m, s, a0, a1, a2, a3);
#pragma unroll
        for (int t = 0; t < 10; ++t) {
            int a = c_anchors[t];
            if (a <= i)
                attn_visit(a, lane, Kb, Vb, q0, q1, q2, q3, m, s, a0, a1, a2, a3);
        }
    }

    float inv = 1.0f / s;
    float* op = g_ctx + ((size_t)(b * L_ + i)) * E_ + h * D_;
    op[lane]      = a0 * inv;
    op[lane + 32] = a1 * inv;
    op[lane + 64] = a2 * inv;
    op[lane + 96] = a3 * inv;
}

// ---------------------------------------------------------------------------
extern "C" void kernel_launch(void* const* d_in, const int* in_sizes, int n_in,
                              void* d_out, int out_size) {
    const float* query = (const float*)d_in[0];
    const float* key_  = (const float*)d_in[1];
    const float* value = (const float*)d_in[2];
    const float* Wq = (const float*)d_in[3];
    const float* bq = (const float*)d_in[4];
    const float* Wk = (const float*)d_in[5];
    const float* bk = (const float*)d_in[6];
    const float* Wv = (const float*)d_in[7];
    const float* bv = (const float*)d_in[8];
    const float* Wo = (const float*)d_in[9];
    const float* bo = (const float*)d_in[10];
    float* out = (float*)d_out;

    float *Qd, *Kd, *Vd, *Cd;
    cudaGetSymbolAddress((void**)&Qd, g_Q);
    cudaGetSymbolAddress((void**)&Kd, g_K);
    cudaGetSymbolAddress((void**)&Vd, g_V);
    cudaGetSymbolAddress((void**)&Cd, g_ctx);

    dim3 ggrid(E_ / 128, (B_ * L_) / 128);   // 8 x 32

    gemm_bias_kernel<<<ggrid, 256>>>(query, Wq, bq, Qd);
    gemm_bias_kernel<<<ggrid, 256>>>(key_,  Wk, bk, Kd);
    gemm_bias_kernel<<<ggrid, 256>>>(value, Wv, bv, Vd);

    int total_warps = B_ * H_ * L_;                 // 32768
    sparse_attn_kernel<<<total_warps * 32 / 256, 256>>>();

    gemm_bias_kernel<<<ggrid, 256>>>(Cd, Wo, bo, out);
}

// round 3
// speedup vs baseline: 1.1809x; 1.1809x over previous
#include <cuda_runtime.h>
#include <math.h>

#define B_ 2
#define L_ 2048
#define E_ 1024
#define H_ 8
#define D_ 128

// Scratch (allocation-free rule: __device__ globals)
__device__ float g_Q[B_ * L_ * E_];
__device__ float g_K[B_ * L_ * E_];
__device__ float g_V[B_ * L_ * E_];
__device__ float g_ctx[B_ * L_ * E_];

// Anchor columns (Skv=2048): unique(int(r*2047)); 0 is covered by the stride-16 loop,
// the rest are all non-multiples of 16, so no duplicate visits.
__constant__ int c_anchors[10] = {204, 409, 614, 781, 1023, 1265, 1432, 1637, 1842, 2047};

// ---------------------------------------------------------------------------
// GEMM: C[m][n] = sum_k A[m*1024+k] * W[n*1024+k] + bias[n]   (NT GEMM)
// 128x128 tile, BK=16, 256 threads, 8x8 microtile.
// ---------------------------------------------------------------------------
__global__ __launch_bounds__(256, 2)
void gemm_bias_kernel(const float* __restrict__ A, const float* __restrict__ W,
                      const float* __restrict__ bias, float* __restrict__ C) {
    const int K = 1024;
    __shared__ float As[16][128];
    __shared__ float Ws[16][128];

    int tid = threadIdx.x;
    int tx = tid & 15;
    int ty = tid >> 4;

    const float* Ag = A + (size_t)blockIdx.y * 128 * K;
    const float* Wg = W + (size_t)blockIdx.x * 128 * K;

    int r0 = tid >> 2;
    int r1 = (tid + 256) >> 2;
    int c0 = (tid & 3) * 4;

    float4 ra0 = *(const float4*)(Ag + (size_t)r0 * K + c0);
    float4 ra1 = *(const float4*)(Ag + (size_t)r1 * K + c0);
    float4 rw0 = *(const float4*)(Wg + (size_t)r0 * K + c0);
    float4 rw1 = *(const float4*)(Wg + (size_t)r1 * K + c0);

    float acc[8][8];
#pragma unroll
    for (int i = 0; i < 8; ++i)
#pragma unroll
        for (int j = 0; j < 8; ++j) acc[i][j] = 0.0f;

    for (int k0 = 0; k0 < K; k0 += 16) {
        As[c0 + 0][r0] = ra0.x; As[c0 + 1][r0] = ra0.y; As[c0 + 2][r0] = ra0.z; As[c0 + 3][r0] = ra0.w;
        As[c0 + 0][r1] = ra1.x; As[c0 + 1][r1] = ra1.y; As[c0 + 2][r1] = ra1.z; As[c0 + 3][r1] = ra1.w;
        Ws[c0 + 0][r0] = rw0.x; Ws[c0 + 1][r0] = rw0.y; Ws[c0 + 2][r0] = rw0.z; Ws[c0 + 3][r0] = rw0.w;
        Ws[c0 + 0][r1] = rw1.x; Ws[c0 + 1][r1] = rw1.y; Ws[c0 + 2][r1] = rw1.z; Ws[c0 + 3][r1] = rw1.w;
        __syncthreads();

        if (k0 + 16 < K) {
            int kn = k0 + 16;
            ra0 = *(const float4*)(Ag + (size_t)r0 * K + kn + c0);
            ra1 = *(const float4*)(Ag + (size_t)r1 * K + kn + c0);
            rw0 = *(const float4*)(Wg + (size_t)r0 * K + kn + c0);
            rw1 = *(const float4*)(Wg + (size_t)r1 * K + kn + c0);
        }

#pragma unroll
        for (int kk = 0; kk < 16; ++kk) {
            float a[8], b[8];
            *(float4*)(a)     = *(const float4*)(&As[kk][ty * 4]);
            *(float4*)(a + 4) = *(const float4*)(&As[kk][64 + ty * 4]);
            *(float4*)(b)     = *(const float4*)(&Ws[kk][tx * 4]);
            *(float4*)(b + 4) = *(const float4*)(&Ws[kk][64 + tx * 4]);
#pragma unroll
            for (int i = 0; i < 8; ++i)
#pragma unroll
                for (int j = 0; j < 8; ++j)
                    acc[i][j] += a[i] * b[j];
        }
        __syncthreads();
    }

    int row_base = blockIdx.y * 128;
    int col_base = blockIdx.x * 128;
#pragma unroll
    for (int ih = 0; ih < 2; ++ih) {
#pragma unroll
        for (int r = 0; r < 4; ++r) {
            int row = row_base + ih * 64 + ty * 4 + r;
            float* Cp = C + (size_t)row * 1024 + col_base;
#pragma unroll
            for (int jh = 0; jh < 2; ++jh) {
                int col = jh * 64 + tx * 4;
                float4 bv = *(const float4*)(bias + col_base + col);
                float4 o;
                o.x = acc[ih * 4 + r][jh * 4 + 0] + bv.x;
                o.y = acc[ih * 4 + r][jh * 4 + 1] + bv.y;
                o.z = acc[ih * 4 + r][jh * 4 + 2] + bv.z;
                o.w = acc[ih * 4 + r][jh * 4 + 3] + bv.w;
                *(float4*)(Cp + col) = o;
            }
        }
    }
}

// ---------------------------------------------------------------------------
// Sparse attention v2: one warp per (b,h,i).
//  - No online max: p = expf(score - 8) is safe (|score| <~ 11) and exact
//    after normalization. Visits are now independent -> ILP.
//  - 4 keys per step: 4 interleaved butterfly reductions share latency.
//  - float4 loads for q, K rows, V rows; float4 coalesced output.
// ---------------------------------------------------------------------------
__device__ __forceinline__ void visit4(
    const float* __restrict__ Kb, const float* __restrict__ Vb,
    int j0, int j1, int j2, int j3, int count,
    float4 q, int lane, float& s, float4& o)
{
    const float4* k0 = (const float4*)(Kb + (size_t)j0 * E_);
    const float4* k1 = (const float4*)(Kb + (size_t)j1 * E_);
    const float4* k2 = (const float4*)(Kb + (size_t)j2 * E_);
    const float4* k3 = (const float4*)(Kb + (size_t)j3 * E_);
    float4 ka = k0[lane];
    float4 kb = k1[lane];
    float4 kc = k2[lane];
    float4 kd = k3[lane];
    float d0 = q.x * ka.x + q.y * ka.y + q.z * ka.z + q.w * ka.w;
    float d1 = q.x * kb.x + q.y * kb.y + q.z * kb.z + q.w * kb.w;
    float d2 = q.x * kc.x + q.y * kc.y + q.z * kc.z + q.w * kc.w;
    float d3 = q.x * kd.x + q.y * kd.y + q.z * kd.z + q.w * kd.w;
#pragma unroll
    for (int off = 16; off > 0; off >>= 1) {
        d0 += __shfl_xor_sync(0xffffffffu, d0, off);
        d1 += __shfl_xor_sync(0xffffffffu, d1, off);
        d2 += __shfl_xor_sync(0xffffffffu, d2, off);
        d3 += __shfl_xor_sync(0xffffffffu, d3, off);
    }
    const float S = 0.08838834764831845f;  // 1/sqrt(128)
    float p0 = __expf(d0 * S - 8.0f);
    float p1 = __expf(d1 * S - 8.0f);
    float p2 = __expf(d2 * S - 8.0f);
    float p3 = __expf(d3 * S - 8.0f);
    if (count < 2) p1 = 0.0f;
    if (count < 3) p2 = 0.0f;
    if (count < 4) p3 = 0.0f;
    s += (p0 + p1) + (p2 + p3);
    const float4* v0 = (const float4*)(Vb + (size_t)j0 * E_);
    const float4* v1 = (const float4*)(Vb + (size_t)j1 * E_);
    const float4* v2 = (const float4*)(Vb + (size_t)j2 * E_);
    const float4* v3 = (const float4*)(Vb + (size_t)j3 * E_);
    float4 va = v0[lane];
    float4 vb = v1[lane];
    float4 vc = v2[lane];
    float4 vd = v3[lane];
    o.x += p0 * va.x + p1 * vb.x + p2 * vc.x + p3 * vd.x;
    o.y += p0 * va.y + p1 * vb.y + p2 * vc.y + p3 * vd.y;
    o.z += p0 * va.z + p1 * vb.z + p2 * vc.z + p3 * vd.z;
    o.w += p0 * va.w + p1 * vb.w + p2 * vc.w + p3 * vd.w;
}

// visit a linear range [lo, hi] (inclusive) with stride st
__device__ __forceinline__ void visit_range(
    const float* __restrict__ Kb, const float* __restrict__ Vb,
    int lo, int hi, int st,
    float4 q, int lane, float& s, float4& o)
{
    for (int j = lo; j <= hi; j += 4 * st) {
        int rem = (hi - j) / st + 1;
        int cnt = rem < 4 ? rem : 4;
        int jb = (cnt > 1) ? j + st     : j;
        int jc = (cnt > 2) ? j + 2 * st : j;
        int jd = (cnt > 3) ? j + 3 * st : j;
        visit4(Kb, Vb, j, jb, jc, jd, cnt, q, lane, s, o);
    }
}

__global__ __launch_bounds__(256)
void sparse_attn_kernel() {
    int gw   = (blockIdx.x * blockDim.x + threadIdx.x) >> 5;  // (b*H+h)*L + i
    int lane = threadIdx.x & 31;
    int i  = gw & (L_ - 1);
    int bh = gw >> 11;
    int h  = bh & (H_ - 1);
    int b  = bh >> 3;

    const float* Qp = g_Q + ((size_t)(b * L_ + i)) * E_ + h * D_;
    float4 q = ((const float4*)Qp)[lane];
    const float* Kb = g_K + (size_t)b * L_ * E_ + h * D_;
    const float* Vb = g_V + (size_t)b * L_ * E_ + h * D_;

    float s = 0.0f;
    float4 o = make_float4(0.0f, 0.0f, 0.0f, 0.0f);

    // head -> cluster: [0,3,3,1,1,1,2,2]
    int cl = (h == 0) ? 0 : (h <= 2) ? 3 : (h <= 5) ? 1 : 2;

    if (cl == 0) {                        // |i-j| <= 8, causal
        int lo = i - 8; if (lo < 0) lo = 0;
        visit_range(Kb, Vb, lo, i, 1, q, lane, s, o);
    } else if (cl == 3) {                 // |i-j| <= 16, causal
        int lo = i - 16; if (lo < 0) lo = 0;
        visit_range(Kb, Vb, lo, i, 1, q, lane, s, o);
    } else if (cl == 1) {                 // |i-j| <= 32 OR j%8==0, causal
        int lo = i - 32; if (lo < 0) lo = 0;
        if (lo > 0)
            visit_range(Kb, Vb, 0, lo - 1 - ((lo - 1) & 7), 8, q, lane, s, o);
        visit_range(Kb, Vb, lo, i, 1, q, lane, s, o);
    } else {                              // j%16==0 OR anchor, causal
        visit_range(Kb, Vb, 0, i - (i & 15), 16, q, lane, s, o);
        // anchors (sorted): count how many are <= i, process prefix in groups of 4
        int cnt = 0;
#pragma unroll
        for (int t = 0; t < 10; ++t)
            if (c_anchors[t] <= i) ++cnt;
        for (int base = 0; base < cnt; base += 4) {
            int c = cnt - base; if (c > 4) c = 4;
            int a0 = c_anchors[base];
            int a1 = c_anchors[(c > 1) ? base + 1 : base];
            int a2 = c_anchors[(c > 2) ? base + 2 : base];
            int a3 = c_anchors[(c > 3) ? base + 3 : base];
            visit4(Kb, Vb, a0, a1, a2, a3, c, q, lane, s, o);
        }
    }

    float inv = 1.0f / s;
    float* op = g_ctx + ((size_t)(b * L_ + i)) * E_ + h * D_;
    float4 r = make_float4(o.x * inv, o.y * inv, o.z * inv, o.w * inv);
    ((float4*)op)[lane] = r;
}

// ---------------------------------------------------------------------------
extern "C" void kernel_launch(void* const* d_in, const int* in_sizes, int n_in,
                              void* d_out, int out_size) {
    const float* query = (const float*)d_in[0];
    const float* key_  = (const float*)d_in[1];
    const float* value = (const float*)d_in[2];
    const float* Wq = (const float*)d_in[3];
    const float* bq = (const float*)d_in[4];
    const float* Wk = (const float*)d_in[5];
    const float* bk = (const float*)d_in[6];
    const float* Wv = (const float*)d_in[7];
    const float* bv = (const float*)d_in[8];
    const float* Wo = (const float*)d_in[9];
    const float* bo = (const float*)d_in[10];
    float* out = (float*)d_out;

    float *Qd, *Kd, *Vd, *Cd;
    cudaGetSymbolAddress((void**)&Qd, g_Q);
    cudaGetSymbolAddress((void**)&Kd, g_K);
    cudaGetSymbolAddress((void**)&Vd, g_V);
    cudaGetSymbolAddress((void**)&Cd, g_ctx);

    dim3 ggrid(E_ / 128, (B_ * L_) / 128);   // 8 x 32

    gemm_bias_kernel<<<ggrid, 256>>>(query, Wq, bq, Qd);
    gemm_bias_kernel<<<ggrid, 256>>>(key_,  Wk, bk, Kd);
    gemm_bias_kernel<<<ggrid, 256>>>(value, Wv, bv, Vd);

    int total_warps = B_ * H_ * L_;                 // 32768
    sparse_attn_kernel<<<total_warps * 32 / 256, 256>>>();

    gemm_bias_kernel<<<ggrid, 256>>>(Cd, Wo, bo, out);
}

// round 5
// speedup vs baseline: 2.1739x; 1.8409x over previous
#include <cuda_runtime.h>
#include <cstdint>
#include <math.h>

#define B_ 2
#define L_ 2048
#define E_ 1024
#define H_ 8
#define D_ 128

// Scratch (allocation-free rule: __device__ globals)
__device__ float g_Q[B_ * L_ * E_];
__device__ float g_K[B_ * L_ * E_];
__device__ float g_V[B_ * L_ * E_];
__device__ float g_ctx[B_ * L_ * E_];

__constant__ int c_anchors[10] = {204, 409, 614, 781, 1023, 1265, 1432, 1637, 1842, 2047};

// ===========================================================================
// helpers
// ===========================================================================
__device__ __forceinline__ uint32_t smem_u32(const void* p) {
    uint32_t a;
    asm("{ .reg .u64 t; cvta.to.shared.u64 t, %1; cvt.u32.u64 %0, t; }" : "=r"(a) : "l"(p));
    return a;
}

// pack two f32 -> bf16x2 (x0 -> low half, x1 -> high half)
__device__ __forceinline__ uint32_t pack_bf16x2(float x0, float x1) {
    uint32_t r;
    asm("cvt.rn.bf16x2.f32 %0, %2, %1;" : "=r"(r) : "f"(x0), "f"(x1));
    return r;
}

__device__ __forceinline__ void ldsm4(uint32_t* r, uint32_t addr) {
    asm volatile("ldmatrix.sync.aligned.m8n8.x4.shared.b16 {%0,%1,%2,%3}, [%4];"
                 : "=r"(r[0]), "=r"(r[1]), "=r"(r[2]), "=r"(r[3]) : "r"(addr));
}

__device__ __forceinline__ void mma_bf16(float* d, const uint32_t* a, const uint32_t* b) {
    asm volatile(
        "mma.sync.aligned.m16n8k16.row.col.f32.bf16.bf16.f32 "
        "{%0,%1,%2,%3}, {%4,%5,%6,%7}, {%8,%9}, {%0,%1,%2,%3};"
        : "+f"(d[0]), "+f"(d[1]), "+f"(d[2]), "+f"(d[3])
        : "r"(a[0]), "r"(a[1]), "r"(a[2]), "r"(a[3]), "r"(b[0]), "r"(b[1]));
}

// ===========================================================================
// Tensor-core GEMM (mma.sync HMMA, split-bf16 hi/lo, fp32 accum):
//   C[4096,1024] = A[4096,1024] @ W[1024,1024]^T + bias
// CTA: 128x128 tile, 256 threads = 8 warps (2 m x 4 n), warp tile 64x32.
// BK = 32, single-buffer SMEM + register prefetch.
// SMEM rows padded to 80 bytes (32 bf16 data + 8 pad) -> conflict-free ldmatrix.
// ===========================================================================
#define LDA 80
#define T_BYTES (128 * LDA)    // 10240 per array
#define AH_OFF 0
#define AL_OFF (T_BYTES)
#define WH_OFF (2 * T_BYTES)
#define WL_OFF (3 * T_BYTES)

__global__ __launch_bounds__(256, 1)
void gemm_tc_kernel(const float* __restrict__ A, const float* __restrict__ W,
                    const float* __restrict__ bias, float* __restrict__ C) {
    __shared__ __align__(16) uint8_t sm[4 * T_BYTES];   // 40960 B
    uint32_t sb = smem_u32(sm);

    int tid = threadIdx.x;
    int lane = tid & 31;
    int wid = tid >> 5;
    int warpM = wid >> 2;       // 0..1  -> m offset *64
    int warpN = wid & 3;        // 0..3  -> n offset *32

    const float* Ag = A + (size_t)blockIdx.y * 128 * 1024;
    const float* Wg = W + (size_t)blockIdx.x * 128 * 1024;

    int r0 = tid >> 3;          // 0..31, rows r0 + i*32
    int c4 = tid & 7;           // float4 index within 32-col row

    // prefetch chunk 0
    float4 pa[4], pw[4];
#pragma unroll
    for (int i = 0; i < 4; ++i) {
        pa[i] = *(const float4*)(Ag + (size_t)(r0 + i * 32) * 1024 + c4 * 4);
        pw[i] = *(const float4*)(Wg + (size_t)(r0 + i * 32) * 1024 + c4 * 4);
    }

    float acc[4][4][4];
#pragma unroll
    for (int f = 0; f < 4; ++f)
#pragma unroll
        for (int g = 0; g < 4; ++g)
#pragma unroll
            for (int r = 0; r < 4; ++r) acc[f][g][r] = 0.0f;

    // ldmatrix source addresses (fixed per thread, add k-step offsets)
    // A-type: rows m0 + (lane&15), k-halves by (lane>>4)
    uint32_t aRow = (uint32_t)(warpM * 64) + (lane & 15);
    uint32_t aAddrBase = aRow * LDA + ((lane >> 4) << 4);
    // B-type: rows n0 + (lane&7) + ((lane>>4)<<3), k-halves by ((lane>>3)&1)
    uint32_t bRow = (uint32_t)(warpN * 32) + (lane & 7) + ((lane >> 4) << 3);
    uint32_t bAddrBase = bRow * LDA + (((lane >> 3) & 1) << 4);

    for (int kt = 0; kt < 32; ++kt) {
        // stage with split-convert
#pragma unroll
        for (int i = 0; i < 4; ++i) {
            uint32_t so = (uint32_t)(r0 + i * 32) * LDA + c4 * 8;
            float4 v = pa[i];
            uint32_t h0 = pack_bf16x2(v.x, v.y);
            uint32_t h1 = pack_bf16x2(v.z, v.w);
            float l0 = v.x - __uint_as_float(h0 << 16);
            float l1 = v.y - __uint_as_float(h0 & 0xFFFF0000u);
            float l2 = v.z - __uint_as_float(h1 << 16);
            float l3 = v.w - __uint_as_float(h1 & 0xFFFF0000u);
            *(uint2*)(sm + AH_OFF + so) = make_uint2(h0, h1);
            *(uint2*)(sm + AL_OFF + so) = make_uint2(pack_bf16x2(l0, l1), pack_bf16x2(l2, l3));
            v = pw[i];
            h0 = pack_bf16x2(v.x, v.y);
            h1 = pack_bf16x2(v.z, v.w);
            l0 = v.x - __uint_as_float(h0 << 16);
            l1 = v.y - __uint_as_float(h0 & 0xFFFF0000u);
            l2 = v.z - __uint_as_float(h1 << 16);
            l3 = v.w - __uint_as_float(h1 & 0xFFFF0000u);
            *(uint2*)(sm + WH_OFF + so) = make_uint2(h0, h1);
            *(uint2*)(sm + WL_OFF + so) = make_uint2(pack_bf16x2(l0, l1), pack_bf16x2(l2, l3));
        }
        __syncthreads();

        if (kt < 31) {
            int k0 = (kt + 1) * 32;
#pragma unroll
            for (int i = 0; i < 4; ++i) {
                pa[i] = *(const float4*)(Ag + (size_t)(r0 + i * 32) * 1024 + k0 + c4 * 4);
                pw[i] = *(const float4*)(Wg + (size_t)(r0 + i * 32) * 1024 + k0 + c4 * 4);
            }
        }

#pragma unroll
        for (int ks = 0; ks < 2; ++ks) {
            uint32_t koff = ks * 32;
            uint32_t bH[2][4], bL[2][4];
            ldsm4(bH[0], sb + WH_OFF + bAddrBase + koff);
            ldsm4(bH[1], sb + WH_OFF + bAddrBase + 16 * LDA + koff);
            ldsm4(bL[0], sb + WL_OFF + bAddrBase + koff);
            ldsm4(bL[1], sb + WL_OFF + bAddrBase + 16 * LDA + koff);
#pragma unroll
            for (int f = 0; f < 4; ++f) {
                uint32_t aH[4], aL[4];
                ldsm4(aH, sb + AH_OFF + aAddrBase + (uint32_t)(f * 16) * LDA + koff);
                ldsm4(aL, sb + AL_OFF + aAddrBase + (uint32_t)(f * 16) * LDA + koff);
#pragma unroll
                for (int g = 0; g < 4; ++g) {
                    const uint32_t* bh = &bH[g >> 1][(g & 1) * 2];
                    const uint32_t* bl = &bL[g >> 1][(g & 1) * 2];
                    mma_bf16(acc[f][g], aH, bh);
                    mma_bf16(acc[f][g], aL, bh);
                    mma_bf16(acc[f][g], aH, bl);
                }
            }
        }
        __syncthreads();
    }

    // epilogue: acc[f][g] is m16n8: d0,d1 @ (row=lane>>2, col=2*(lane&3)), d2,d3 @ row+8
    int crow = blockIdx.y * 128 + warpM * 64 + (lane >> 2);
    int ccol0 = blockIdx.x * 128 + warpN * 32 + (lane & 3) * 2;
#pragma unroll
    for (int g = 0; g < 4; ++g) {
        int c = ccol0 + g * 8;
        float2 bv = *(const float2*)(bias + c);
#pragma unroll
        for (int f = 0; f < 4; ++f) {
            int r = crow + f * 16;
            float2 o0 = make_float2(acc[f][g][0] + bv.x, acc[f][g][1] + bv.y);
            float2 o1 = make_float2(acc[f][g][2] + bv.x, acc[f][g][3] + bv.y);
            *(float2*)(C + (size_t)r * 1024 + c) = o0;
            *(float2*)(C + (size_t)(r + 8) * 1024 + c) = o1;
        }
    }
}

// ===========================================================================
// Sparse attention (R3 version — near L1 floor, unchanged)
// ===========================================================================
__device__ __forceinline__ void visit4(
    const float* __restrict__ Kb, const float* __restrict__ Vb,
    int j0, int j1, int j2, int j3, int count,
    float4 q, int lane, float& s, float4& o)
{
    const float4* k0 = (const float4*)(Kb + (size_t)j0 * E_);
    const float4* k1 = (const float4*)(Kb + (size_t)j1 * E_);
    const float4* k2 = (const float4*)(Kb + (size_t)j2 * E_);
    const float4* k3 = (const float4*)(Kb + (size_t)j3 * E_);
    float4 ka = k0[lane];
    float4 kb = k1[lane];
    float4 kc = k2[lane];
    float4 kd = k3[lane];
    float d0 = q.x * ka.x + q.y * ka.y + q.z * ka.z + q.w * ka.w;
    float d1 = q.x * kb.x + q.y * kb.y + q.z * kb.z + q.w * kb.w;
    float d2 = q.x * kc.x + q.y * kc.y + q.z * kc.z + q.w * kc.w;
    float d3 = q.x * kd.x + q.y * kd.y + q.z * kd.z + q.w * kd.w;
#pragma unroll
    for (int off = 16; off > 0; off >>= 1) {
        d0 += __shfl_xor_sync(0xffffffffu, d0, off);
        d1 += __shfl_xor_sync(0xffffffffu, d1, off);
        d2 += __shfl_xor_sync(0xffffffffu, d2, off);
        d3 += __shfl_xor_sync(0xffffffffu, d3, off);
    }
    const float S = 0.08838834764831845f;  // 1/sqrt(128)
    float p0 = __expf(d0 * S - 8.0f);
    float p1 = __expf(d1 * S - 8.0f);
    float p2 = __expf(d2 * S - 8.0f);
    float p3 = __expf(d3 * S - 8.0f);
    if (count < 2) p1 = 0.0f;
    if (count < 3) p2 = 0.0f;
    if (count < 4) p3 = 0.0f;
    s += (p0 + p1) + (p2 + p3);
    const float4* v0 = (const float4*)(Vb + (size_t)j0 * E_);
    const float4* v1 = (const float4*)(Vb + (size_t)j1 * E_);
    const float4* v2 = (const float4*)(Vb + (size_t)j2 * E_);
    const float4* v3 = (const float4*)(Vb + (size_t)j3 * E_);
    float4 va = v0[lane];
    float4 vb = v1[lane];
    float4 vc = v2[lane];
    float4 vd = v3[lane];
    o.x += p0 * va.x + p1 * vb.x + p2 * vc.x + p3 * vd.x;
    o.y += p0 * va.y + p1 * vb.y + p2 * vc.y + p3 * vd.y;
    o.z += p0 * va.z + p1 * vb.z + p2 * vc.z + p3 * vd.z;
    o.w += p0 * va.w + p1 * vb.w + p2 * vc.w + p3 * vd.w;
}

__device__ __forceinline__ void visit_range(
    const float* __restrict__ Kb, const float* __restrict__ Vb,
    int lo, int hi, int st,
    float4 q, int lane, float& s, float4& o)
{
    for (int j = lo; j <= hi; j += 4 * st) {
        int rem = (hi - j) / st + 1;
        int cnt = rem < 4 ? rem : 4;
        int jb = (cnt > 1) ? j + st     : j;
        int jc = (cnt > 2) ? j + 2 * st : j;
        int jd = (cnt > 3) ? j + 3 * st : j;
        visit4(Kb, Vb, j, jb, jc, jd, cnt, q, lane, s, o);
    }
}

__global__ __launch_bounds__(256)
void sparse_attn_kernel() {
    int gw   = (blockIdx.x * blockDim.x + threadIdx.x) >> 5;
    int lane = threadIdx.x & 31;
    int i  = gw & (L_ - 1);
    int bh = gw >> 11;
    int h  = bh & (H_ - 1);
    int b  = bh >> 3;

    const float* Qp = g_Q + ((size_t)(b * L_ + i)) * E_ + h * D_;
    float4 q = ((const float4*)Qp)[lane];
    const float* Kb = g_K + (size_t)b * L_ * E_ + h * D_;
    const float* Vb = g_V + (size_t)b * L_ * E_ + h * D_;

    float s = 0.0f;
    float4 o = make_float4(0.0f, 0.0f, 0.0f, 0.0f);

    int cl = (h == 0) ? 0 : (h <= 2) ? 3 : (h <= 5) ? 1 : 2;

    if (cl == 0) {
        int lo = i - 8; if (lo < 0) lo = 0;
        visit_range(Kb, Vb, lo, i, 1, q, lane, s, o);
    } else if (cl == 3) {
        int lo = i - 16; if (lo < 0) lo = 0;
        visit_range(Kb, Vb, lo, i, 1, q, lane, s, o);
    } else if (cl == 1) {
        int lo = i - 32; if (lo < 0) lo = 0;
        if (lo > 0)
            visit_range(Kb, Vb, 0, lo - 1 - ((lo - 1) & 7), 8, q, lane, s, o);
        visit_range(Kb, Vb, lo, i, 1, q, lane, s, o);
    } else {
        visit_range(Kb, Vb, 0, i - (i & 15), 16, q, lane, s, o);
        int cnt = 0;
#pragma unroll
        for (int t = 0; t < 10; ++t)
            if (c_anchors[t] <= i) ++cnt;
        for (int base = 0; base < cnt; base += 4) {
            int c = cnt - base; if (c > 4) c = 4;
            int a0 = c_anchors[base];
            int a1 = c_anchors[(c > 1) ? base + 1 : base];
            int a2 = c_anchors[(c > 2) ? base + 2 : base];
            int a3 = c_anchors[(c > 3) ? base + 3 : base];
            visit4(Kb, Vb, a0, a1, a2, a3, c, q, lane, s, o);
        }
    }

    float inv = 1.0f / s;
    float* op = g_ctx + ((size_t)(b * L_ + i)) * E_ + h * D_;
    float4 r = make_float4(o.x * inv, o.y * inv, o.z * inv, o.w * inv);
    ((float4*)op)[lane] = r;
}

// ---------------------------------------------------------------------------
extern "C" void kernel_launch(void* const* d_in, const int* in_sizes, int n_in,
                              void* d_out, int out_size) {
    const float* query = (const float*)d_in[0];
    const float* key_  = (const float*)d_in[1];
    const float* value = (const float*)d_in[2];
    const float* Wq = (const float*)d_in[3];
    const float* bq = (const float*)d_in[4];
    const float* Wk = (const float*)d_in[5];
    const float* bk = (const float*)d_in[6];
    const float* Wv = (const float*)d_in[7];
    const float* bv = (const float*)d_in[8];
    const float* Wo = (const float*)d_in[9];
    const float* bo = (const float*)d_in[10];
    float* out = (float*)d_out;

    float *Qd, *Kd, *Vd, *Cd;
    cudaGetSymbolAddress((void**)&Qd, g_Q);
    cudaGetSymbolAddress((void**)&Kd, g_K);
    cudaGetSymbolAddress((void**)&Vd, g_V);
    cudaGetSymbolAddress((void**)&Cd, g_ctx);

    dim3 ggrid(E_ / 128, (B_ * L_) / 128);   // 8 x 32 = 256 CTAs

    gemm_tc_kernel<<<ggrid, 256>>>(query, Wq, bq, Qd);
    gemm_tc_kernel<<<ggrid, 256>>>(key_,  Wk, bk, Kd);
    gemm_tc_kernel<<<ggrid, 256>>>(value, Wv, bv, Vd);

    int total_warps = B_ * H_ * L_;                 // 32768
    sparse_attn_kernel<<<total_warps * 32 / 256, 256>>>();

    gemm_tc_kernel<<<ggrid, 256>>>(Cd, Wo, bo, out);
}